// round 6
// baseline (speedup 1.0000x reference)
#include <cuda_runtime.h>
#include <cstdint>

// Problem constants
#define BATCH 2
#define SEQ   2048
#define DMODEL 1024
#define NHEAD 16
#define HDIM  64
#define BH    (BATCH*NHEAD)          // 32
#define MROWS (BATCH*SEQ)            // 4096

// Scratch (device globals: allocation-free per harness rules)
__device__ float g_q[BH * SEQ * HDIM];     // [bh][s][hd]
__device__ float g_k[BH * SEQ * HDIM];
__device__ float g_v[BH * SEQ * HDIM];
__device__ float g_ctx[MROWS * DMODEL];    // [b*S+s][d]

// ---------------------------------------------------------------------------
// helpers
// ---------------------------------------------------------------------------
__device__ __forceinline__ uint32_t f2tf32(float x) {
    uint32_t r;
    asm("cvt.rna.tf32.f32 %0, %1;" : "=r"(r) : "f"(x));
    return r;
}

// async 16B copy gmem -> smem (bypass L1 at destination side: .cg)
__device__ __forceinline__ void cp16(void* smem_dst, const void* gsrc) {
    uint32_t d;
    asm("{ .reg .u64 t; cvta.to.shared.u64 t, %1; cvt.u32.u64 %0, t; }"
        : "=r"(d) : "l"(smem_dst));
    asm volatile("cp.async.cg.shared.global [%0], [%1], 16;" :: "r"(d), "l"(gsrc));
}
#define CP_COMMIT() asm volatile("cp.async.commit_group;" ::: "memory")
#define CP_WAIT1()  asm volatile("cp.async.wait_group 1;" ::: "memory")
#define CP_WAIT0()  asm volatile("cp.async.wait_group 0;" ::: "memory")

// mma.m16n8k8 tf32, D += A*B (C aliased to D)
__device__ __forceinline__ void mma8(float* d, const uint32_t* a, const uint32_t* b) {
    asm volatile(
        "mma.sync.aligned.m16n8k8.row.col.f32.tf32.tf32.f32 "
        "{%0,%1,%2,%3}, {%4,%5,%6,%7}, {%8,%9}, {%0,%1,%2,%3};\n"
        : "+f"(d[0]), "+f"(d[1]), "+f"(d[2]), "+f"(d[3])
        : "r"(a[0]), "r"(a[1]), "r"(a[2]), "r"(a[3]), "r"(b[0]), "r"(b[1]));
}

// fast 2^y for y <= 0 (clamped at -80), FMA-pipe only, rel err ~3e-6
__device__ __forceinline__ float exp2p(float y) {
    y = fmaxf(y, -80.f);
    int e = __float2int_rn(y);
    float f = y - (float)e;
    float p = 1.3333558e-3f;
    p = fmaf(p, f, 9.6181291e-3f);
    p = fmaf(p, f, 5.5504109e-2f);
    p = fmaf(p, f, 2.4022651e-1f);
    p = fmaf(p, f, 6.9314718e-1f);
    p = fmaf(p, f, 1.0f);
    return __int_as_float(__float_as_int(p) + (e << 23));
}

// ---------------------------------------------------------------------------
// tf32 mma.sync GEMM: C[M,N] = A[M,K] @ B[K,N] + bias.
// Tile 128x128x32, 256 threads, 8 warps (2m x 4n), warp tile 64x32.
// cp.async 2-stage pipeline; smem natural layout; cvt.rna.tf32 at frag load.
// mode 0: write C ; mode 1: scatter into g_q/g_k/g_v (QKV head layout)
// ---------------------------------------------------------------------------
#define GEMM_STG_F (128*36 + 32*132)          // 8832 floats per stage
#define GEMM_SMEM  (2 * GEMM_STG_F * 4)       // 70,656 B

__device__ __forceinline__ void gemm_stage_async(
    float* sm, int s, const float* __restrict__ A, const float* __restrict__ Bm,
    int m0, int n0, int kt, int K, int N, int tid)
{
    float* As = sm + s * GEMM_STG_F;
    float* Bs = As + 128 * 36;
#pragma unroll
    for (int i = 0; i < 4; i++) {
        int f = tid + i * 256;
        int row = f >> 3, c0 = (f & 7) * 4;
        cp16(&As[row * 36 + c0], A + (size_t)(m0 + row) * K + kt + c0);
    }
#pragma unroll
    for (int i = 0; i < 4; i++) {
        int f = tid + i * 256;
        int kr = f >> 5, c0 = (f & 31) * 4;
        cp16(&Bs[kr * 132 + c0], Bm + (size_t)(kt + kr) * N + n0 + c0);
    }
}

__global__ __launch_bounds__(256, 2) void gemm_tc(
    const float* __restrict__ A, const float* __restrict__ Bm,
    const float* __restrict__ bias, float* __restrict__ C,
    int M, int N, int K, int mode)
{
    extern __shared__ float sm[];

    const int tid  = threadIdx.x;
    const int wid  = tid >> 5;
    const int lane = tid & 31;
    const int g = lane >> 2, t = lane & 3;
    const int wm = wid >> 2, wn = wid & 3;
    const int m0 = blockIdx.y * 128;
    const int n0 = blockIdx.x * 128;

    float acc[4][4][4];
#pragma unroll
    for (int mt = 0; mt < 4; mt++)
#pragma unroll
        for (int nt = 0; nt < 4; nt++)
#pragma unroll
            for (int j = 0; j < 4; j++) acc[mt][nt][j] = 0.f;

    const int T = K / 32;   // 32
    gemm_stage_async(sm, 0, A, Bm, m0, n0, 0, K, N, tid);
    CP_COMMIT();
    gemm_stage_async(sm, 1, A, Bm, m0, n0, 32, K, N, tid);
    CP_COMMIT();
    CP_WAIT1();
    __syncthreads();

    for (int tt = 0; tt < T; tt++) {
        const float* As = sm + (tt & 1) * GEMM_STG_F;
        const float* Bs = As + 128 * 36;
#pragma unroll
        for (int ks = 0; ks < 4; ks++) {
            uint32_t bb[4][2];
#pragma unroll
            for (int nt = 0; nt < 4; nt++) {
                int col = wn * 32 + nt * 8 + g;
                bb[nt][0] = f2tf32(Bs[(ks * 8 + t) * 132 + col]);
                bb[nt][1] = f2tf32(Bs[(ks * 8 + t + 4) * 132 + col]);
            }
#pragma unroll
            for (int mt = 0; mt < 4; mt++) {
                int rb = wm * 64 + mt * 16;
                uint32_t aa[4];
                aa[0] = f2tf32(As[(rb + g) * 36 + ks * 8 + t]);
                aa[1] = f2tf32(As[(rb + g + 8) * 36 + ks * 8 + t]);
                aa[2] = f2tf32(As[(rb + g) * 36 + ks * 8 + t + 4]);
                aa[3] = f2tf32(As[(rb + g + 8) * 36 + ks * 8 + t + 4]);
#pragma unroll
                for (int nt = 0; nt < 4; nt++)
                    mma8(acc[mt][nt], aa, bb[nt]);
            }
        }
        __syncthreads();   // all warps done reading buf (tt&1)
        if (tt + 2 < T) {
            gemm_stage_async(sm, tt & 1, A, Bm, m0, n0, (tt + 2) * 32, K, N, tid);
            CP_COMMIT();
            CP_WAIT1();    // group (tt+1) complete
        } else {
            CP_WAIT0();
        }
        __syncthreads();   // buf (tt+1)&1 visible to all
    }

    // epilogue: direct fragment stores (+bias)
#pragma unroll
    for (int mt = 0; mt < 4; mt++) {
        int r0 = m0 + wm * 64 + mt * 16 + g;
        int r1 = r0 + 8;
#pragma unroll
        for (int nt = 0; nt < 4; nt++) {
            int col = n0 + wn * 32 + nt * 8 + 2 * t;
            float2 b2 = *(const float2*)(bias + col);
            float2 v0 = { acc[mt][nt][0] + b2.x, acc[mt][nt][1] + b2.y };
            float2 v1 = { acc[mt][nt][2] + b2.x, acc[mt][nt][3] + b2.y };
            if (mode == 0) {
                *(float2*)(C + (size_t)r0 * N + col) = v0;
                *(float2*)(C + (size_t)r1 * N + col) = v1;
            } else {
                int part = col >> 10;
                int rr   = col & 1023;
                int h    = rr >> 6;
                int hd   = rr & 63;
                float* dst = (part == 0) ? g_q : (part == 1) ? g_k : g_v;
                int b0i = r0 >> 11, s0 = r0 & 2047;
                int b1i = r1 >> 11, s1 = r1 & 2047;
                *(float2*)(dst + ((size_t)(b0i * NHEAD + h) * SEQ + s0) * HDIM + hd) = v0;
                *(float2*)(dst + ((size_t)(b1i * NHEAD + h) * SEQ + s1) * HDIM + hd) = v1;
            }
        }
    }
}

// ---------------------------------------------------------------------------
// Tensor-core causal flash attention (tf32 mma.sync), cp.async pipeline.
// CTA: 256 threads (8 warps), BM=128 (16 rows/warp), BN=64 keys/tile.
// smem floats: Qs[128*68] (per-warp region reused as P), then 2 stages of
// (K[64*68] + V[64*68]).
// ---------------------------------------------------------------------------
#define ATT_QF   (128 * 68)                   // 8704
#define ATT_KVF  (2 * 64 * 68)                // 8704 per stage
#define ATT_SMEM ((ATT_QF + 2 * ATT_KVF) * 4) // 104,448 B

__device__ __forceinline__ void attn_stage_kv_async(
    float* base, int s, const float* __restrict__ kbp, const float* __restrict__ vbp,
    int kb, int tid)
{
    float* Ks = base + ATT_QF + s * ATT_KVF;
    float* Vs = Ks + 64 * 68;
#pragma unroll
    for (int i = 0; i < 4; i++) {
        int f = tid + i * 256;
        int row = f >> 4, c0 = (f & 15) * 4;
        cp16(&Ks[row * 68 + c0], kbp + (size_t)(kb + row) * HDIM + c0);
        cp16(&Vs[row * 68 + c0], vbp + (size_t)(kb + row) * HDIM + c0);
    }
}

__global__ __launch_bounds__(256, 2) void attn_tc()
{
    extern __shared__ float smx[];
    float* Qs = smx;

    const int tid  = threadIdx.x;
    const int wid  = tid >> 5;
    const int lane = tid & 31;
    const int g = lane >> 2, t = lane & 3;
    const int bh = blockIdx.y;
    const int m0 = ((int)gridDim.x - 1 - (int)blockIdx.x) * 128;  // heavy first

    const float* qb  = g_q + (size_t)bh * SEQ * HDIM;
    const float* kbp = g_k + (size_t)bh * SEQ * HDIM;
    const float* vbp = g_v + (size_t)bh * SEQ * HDIM;

    const int ntile = m0 / 64 + 2;           // >= 2 always

    // prologue: Q + KV tile0 in group 0, KV tile1 in group 1
#pragma unroll
    for (int i = 0; i < 8; i++) {
        int f = tid + i * 256;
        int row = f >> 4, c0 = (f & 15) * 4;
        cp16(&Qs[row * 68 + c0], qb + (size_t)(m0 + row) * HDIM + c0);
    }
    attn_stage_kv_async(smx, 0, kbp, vbp, 0, tid);
    CP_COMMIT();
    attn_stage_kv_async(smx, 1, kbp, vbp, 64, tid);
    CP_COMMIT();
    CP_WAIT1();          // group 0 (Q + KV0) complete
    __syncthreads();

    // Q fragments (cvt at load); warp's Q rows become its private P region
    uint32_t qa[8][4];
    {
        int rb = wid * 16;
#pragma unroll
        for (int ks = 0; ks < 8; ks++) {
            qa[ks][0] = f2tf32(Qs[(rb + g) * 68 + ks * 8 + t]);
            qa[ks][1] = f2tf32(Qs[(rb + g + 8) * 68 + ks * 8 + t]);
            qa[ks][2] = f2tf32(Qs[(rb + g) * 68 + ks * 8 + t + 4]);
            qa[ks][3] = f2tf32(Qs[(rb + g + 8) * 68 + ks * 8 + t + 4]);
        }
    }

    float o[8][4];
#pragma unroll
    for (int nt = 0; nt < 8; nt++)
#pragma unroll
        for (int j = 0; j < 4; j++) o[nt][j] = 0.f;
    float mlo = -1e30f, mhi = -1e30f, llo = 0.f, lhi = 0.f;

    const float SC = 0.125f * 1.44269504f;   // score scale, base-2 domain

    for (int tt = 0; tt < ntile; tt++) {
        const int kb = tt * 64;
        const float* Kc = smx + ATT_QF + (tt & 1) * ATT_KVF;
        const float* Vc = Kc + 64 * 68;

        // S = Q @ K^T  (warp: 16 x 64), cvt K at load
        float s[8][4];
#pragma unroll
        for (int nt = 0; nt < 8; nt++)
#pragma unroll
            for (int j = 0; j < 4; j++) s[nt][j] = 0.f;
#pragma unroll
        for (int ks = 0; ks < 8; ks++) {
#pragma unroll
            for (int nt = 0; nt < 8; nt++) {
                uint32_t bb[2];
                bb[0] = f2tf32(Kc[(nt * 8 + g) * 68 + ks * 8 + t]);
                bb[1] = f2tf32(Kc[(nt * 8 + g) * 68 + ks * 8 + t + 4]);
                mma8(s[nt], qa[ks], bb);
            }
        }

        // scale (+ causal mask near diagonal)
        const int rlo = m0 + wid * 16 + g;
        const int rhi = rlo + 8;
        if (kb + 63 > m0 + wid * 16) {
#pragma unroll
            for (int nt = 0; nt < 8; nt++) {
                int c0 = kb + nt * 8 + 2 * t;
                s[nt][0] = (c0     > rlo) ? -1e30f : s[nt][0] * SC;
                s[nt][1] = (c0 + 1 > rlo) ? -1e30f : s[nt][1] * SC;
                s[nt][2] = (c0     > rhi) ? -1e30f : s[nt][2] * SC;
                s[nt][3] = (c0 + 1 > rhi) ? -1e30f : s[nt][3] * SC;
            }
        } else {
#pragma unroll
            for (int nt = 0; nt < 8; nt++)
#pragma unroll
                for (int j = 0; j < 4; j++) s[nt][j] *= SC;
        }

        // row max (quad reduction)
        float tlo = -1e30f, thi = -1e30f;
#pragma unroll
        for (int nt = 0; nt < 8; nt++) {
            tlo = fmaxf(tlo, fmaxf(s[nt][0], s[nt][1]));
            thi = fmaxf(thi, fmaxf(s[nt][2], s[nt][3]));
        }
        tlo = fmaxf(tlo, __shfl_xor_sync(0xffffffff, tlo, 1));
        tlo = fmaxf(tlo, __shfl_xor_sync(0xffffffff, tlo, 2));
        thi = fmaxf(thi, __shfl_xor_sync(0xffffffff, thi, 1));
        thi = fmaxf(thi, __shfl_xor_sync(0xffffffff, thi, 2));

        float nmlo = fmaxf(mlo, tlo), nmhi = fmaxf(mhi, thi);
        float alo = exp2p(mlo - nmlo), ahi = exp2p(mhi - nmhi);
        mlo = nmlo; mhi = nmhi;

        // p = 2^(s-m), partial sums
        float slo = 0.f, shi = 0.f;
#pragma unroll
        for (int nt = 0; nt < 8; nt++) {
            s[nt][0] = exp2p(s[nt][0] - mlo);
            s[nt][1] = exp2p(s[nt][1] - mlo);
            s[nt][2] = exp2p(s[nt][2] - mhi);
            s[nt][3] = exp2p(s[nt][3] - mhi);
            slo += s[nt][0] + s[nt][1];
            shi += s[nt][2] + s[nt][3];
        }
        slo += __shfl_xor_sync(0xffffffff, slo, 1);
        slo += __shfl_xor_sync(0xffffffff, slo, 2);
        shi += __shfl_xor_sync(0xffffffff, shi, 1);
        shi += __shfl_xor_sync(0xffffffff, shi, 2);
        llo = llo * alo + slo;
        lhi = lhi * ahi + shi;

        // rescale O
#pragma unroll
        for (int nt = 0; nt < 8; nt++) {
            o[nt][0] *= alo; o[nt][1] *= alo;
            o[nt][2] *= ahi; o[nt][3] *= ahi;
        }

        // P -> warp-private 16x68 region (tf32 bits), then O += P @ V
        float* Ps = Qs + wid * (16 * 68);
#pragma unroll
        for (int nt = 0; nt < 8; nt++) {
            int c = nt * 8 + 2 * t;
            uint2 plo = { f2tf32(s[nt][0]), f2tf32(s[nt][1]) };
            uint2 phi = { f2tf32(s[nt][2]), f2tf32(s[nt][3]) };
            *(uint2*)&Ps[g * 68 + c]       = plo;
            *(uint2*)&Ps[(g + 8) * 68 + c] = phi;
        }
        __syncwarp();

#pragma unroll
        for (int ks = 0; ks < 8; ks++) {
            uint32_t aa[4];
            aa[0] = __float_as_uint(Ps[g * 68 + ks * 8 + t]);
            aa[1] = __float_as_uint(Ps[(g + 8) * 68 + ks * 8 + t]);
            aa[2] = __float_as_uint(Ps[g * 68 + ks * 8 + t + 4]);
            aa[3] = __float_as_uint(Ps[(g + 8) * 68 + ks * 8 + t + 4]);
#pragma unroll
            for (int nt = 0; nt < 8; nt++) {
                uint32_t bb[2];
                bb[0] = f2tf32(Vc[(ks * 8 + t) * 68 + nt * 8 + g]);
                bb[1] = f2tf32(Vc[(ks * 8 + t + 4) * 68 + nt * 8 + g]);
                mma8(o[nt], aa, bb);
            }
        }

        __syncthreads();   // all warps done reading KV buf (tt&1)
        if (tt + 2 < ntile) {
            attn_stage_kv_async(smx, tt & 1, kbp, vbp, (tt + 2) * 64, tid);
            CP_COMMIT();
            CP_WAIT1();
        } else {
            CP_WAIT0();
        }
        __syncthreads();
    }

    // epilogue: O /= l, write to ctx
    const float ilo = 1.f / llo, ihi = 1.f / lhi;
    const int rlo = m0 + wid * 16 + g;
    const int rhi = rlo + 8;
    const int bidx = bh >> 4, h = bh & 15;
    float* clo = g_ctx + ((size_t)(bidx * SEQ + rlo)) * DMODEL + h * HDIM;
    float* chi = g_ctx + ((size_t)(bidx * SEQ + rhi)) * DMODEL + h * HDIM;
#pragma unroll
    for (int nt = 0; nt < 8; nt++) {
        int c = nt * 8 + 2 * t;
        float2 v0 = { o[nt][0] * ilo, o[nt][1] * ilo };
        float2 v1 = { o[nt][2] * ihi, o[nt][3] * ihi };
        *(float2*)(clo + c) = v0;
        *(float2*)(chi + c) = v1;
    }
}

// ---------------------------------------------------------------------------
extern "C" void kernel_launch(void* const* d_in, const int* in_sizes, int n_in,
                              void* d_out, int out_size)
{
    const float* x      = (const float*)d_in[0];   // [B,S,D]
    const float* w_qkv  = (const float*)d_in[1];   // [D, 3D]
    const float* b_qkv  = (const float*)d_in[2];   // [3D]
    const float* w_proj = (const float*)d_in[3];   // [D, D]
    const float* b_proj = (const float*)d_in[4];   // [D]
    float* out = (float*)d_out;                    // [B,S,D]

    float* ctx;
    cudaGetSymbolAddress((void**)&ctx, g_ctx);

    cudaFuncSetAttribute(gemm_tc, cudaFuncAttributeMaxDynamicSharedMemorySize, GEMM_SMEM);
    cudaFuncSetAttribute(attn_tc, cudaFuncAttributeMaxDynamicSharedMemorySize, ATT_SMEM);

    // 1) QKV projection -> g_q/g_k/g_v
    {
        dim3 grid(3 * DMODEL / 128, MROWS / 128);  // (24, 32)
        gemm_tc<<<grid, 256, GEMM_SMEM>>>(x, w_qkv, b_qkv, nullptr,
                                          MROWS, 3 * DMODEL, DMODEL, /*mode=*/1);
    }
    // 2) causal attention -> g_ctx
    {
        dim3 grid(SEQ / 128, BH);                  // (16, 32)
        attn_tc<<<grid, 256, ATT_SMEM>>>();
    }
    // 3) output projection -> d_out
    {
        dim3 grid(DMODEL / 128, MROWS / 128);      // (8, 32)
        gemm_tc<<<grid, 256, GEMM_SMEM>>>(ctx, w_proj, b_proj, out,
                                          MROWS, DMODEL, DMODEL, /*mode=*/0);
    }
    (void)in_sizes; (void)n_in; (void)out_size;
}

// round 7
// speedup vs baseline: 1.0979x; 1.0979x over previous
#include <cuda_runtime.h>
#include <cstdint>

// Problem constants
#define BATCH 2
#define SEQ   2048
#define DMODEL 1024
#define NHEAD 16
#define HDIM  64
#define BH    (BATCH*NHEAD)          // 32
#define MROWS (BATCH*SEQ)            // 4096

// Scratch (device globals: allocation-free per harness rules)
__device__ float g_x[MROWS * DMODEL];          // tf32-rounded x
__device__ float g_wqkv[DMODEL * 3 * DMODEL];  // tf32-rounded w_qkv
__device__ float g_wproj[DMODEL * DMODEL];     // tf32-rounded w_proj
__device__ float g_q[BH * SEQ * HDIM];         // [bh][s][hd] (tf32-rounded)
__device__ float g_k[BH * SEQ * HDIM];
__device__ float g_v[BH * SEQ * HDIM];
__device__ float g_ctx[MROWS * DMODEL];        // [b*S+s][d] (tf32-rounded)

// ---------------------------------------------------------------------------
// helpers
// ---------------------------------------------------------------------------
__device__ __forceinline__ uint32_t f2tf32(float x) {
    uint32_t r;
    asm("cvt.rna.tf32.f32 %0, %1;" : "=r"(r) : "f"(x));
    return r;
}
__device__ __forceinline__ float tff(float x) {        // tf32-rounded, as float
    return __uint_as_float(f2tf32(x));
}
__device__ __forceinline__ float ex2f(float x) {       // 2^x via MUFU
    float r;
    asm("ex2.approx.f32 %0, %1;" : "=f"(r) : "f"(x));
    return r;
}

// async 16B copy gmem -> smem
__device__ __forceinline__ void cp16(void* smem_dst, const void* gsrc) {
    uint32_t d;
    asm("{ .reg .u64 t; cvta.to.shared.u64 t, %1; cvt.u32.u64 %0, t; }"
        : "=r"(d) : "l"(smem_dst));
    asm volatile("cp.async.cg.shared.global [%0], [%1], 16;" :: "r"(d), "l"(gsrc));
}
#define CP_COMMIT() asm volatile("cp.async.commit_group;" ::: "memory")
#define CP_WAIT1()  asm volatile("cp.async.wait_group 1;" ::: "memory")
#define CP_WAIT0()  asm volatile("cp.async.wait_group 0;" ::: "memory")

// mma.m16n8k8 tf32, D += A*B (C aliased to D)
__device__ __forceinline__ void mma8(float* d, const uint32_t* a, const uint32_t* b) {
    asm volatile(
        "mma.sync.aligned.m16n8k8.row.col.f32.tf32.tf32.f32 "
        "{%0,%1,%2,%3}, {%4,%5,%6,%7}, {%8,%9}, {%0,%1,%2,%3};\n"
        : "+f"(d[0]), "+f"(d[1]), "+f"(d[2]), "+f"(d[3])
        : "r"(a[0]), "r"(a[1]), "r"(a[2]), "r"(a[3]), "r"(b[0]), "r"(b[1]));
}

// ---------------------------------------------------------------------------
// tf32 pre-round pass (grid-stride over float4)
// ---------------------------------------------------------------------------
__global__ void tf32_round_kernel(const float4* __restrict__ in,
                                  float4* __restrict__ out, int n4)
{
    for (int i = blockIdx.x * blockDim.x + threadIdx.x; i < n4;
         i += gridDim.x * blockDim.x) {
        float4 v = in[i];
        float4 o = { tff(v.x), tff(v.y), tff(v.z), tff(v.w) };
        out[i] = o;
    }
}

// ---------------------------------------------------------------------------
// tf32 mma.sync GEMM: C[M,N] = A[M,K] @ B[K,N] + bias. Inputs pre-rounded.
// Tile 128x128x32, 256 threads, 8 warps (2m x 4n), warp tile 64x32.
// 3-stage cp.async ring, one barrier per k-tile. No cvt in mainloop.
// mode 0: write C raw f32 ; mode 1: scatter tf32-rounded q/k/v
// ---------------------------------------------------------------------------
#define GEMM_STG_F (128*36 + 32*132)          // 8832 floats per stage
#define GEMM_SMEM  (3 * GEMM_STG_F * 4)       // 105,984 B

__device__ __forceinline__ void gemm_stage_async(
    float* sm, int s, const float* __restrict__ A, const float* __restrict__ Bm,
    int m0, int n0, int kt, int K, int N, int tid)
{
    float* As = sm + s * GEMM_STG_F;
    float* Bs = As + 128 * 36;
#pragma unroll
    for (int i = 0; i < 4; i++) {
        int f = tid + i * 256;
        int row = f >> 3, c0 = (f & 7) * 4;
        cp16(&As[row * 36 + c0], A + (size_t)(m0 + row) * K + kt + c0);
    }
#pragma unroll
    for (int i = 0; i < 4; i++) {
        int f = tid + i * 256;
        int kr = f >> 5, c0 = (f & 31) * 4;
        cp16(&Bs[kr * 132 + c0], Bm + (size_t)(kt + kr) * N + n0 + c0);
    }
}

__global__ __launch_bounds__(256, 2) void gemm_tc(
    const float* __restrict__ A, const float* __restrict__ Bm,
    const float* __restrict__ bias, float* __restrict__ C,
    int M, int N, int K, int mode)
{
    extern __shared__ float sm[];

    const int tid  = threadIdx.x;
    const int wid  = tid >> 5;
    const int lane = tid & 31;
    const int g = lane >> 2, t = lane & 3;
    const int wm = wid >> 2, wn = wid & 3;
    const int m0 = blockIdx.y * 128;
    const int n0 = blockIdx.x * 128;

    float acc[4][4][4];
#pragma unroll
    for (int mt = 0; mt < 4; mt++)
#pragma unroll
        for (int nt = 0; nt < 4; nt++)
#pragma unroll
            for (int j = 0; j < 4; j++) acc[mt][nt][j] = 0.f;

    const int T = K / 32;   // 32
    gemm_stage_async(sm, 0, A, Bm, m0, n0, 0, K, N, tid);
    CP_COMMIT();
    gemm_stage_async(sm, 1, A, Bm, m0, n0, 32, K, N, tid);
    CP_COMMIT();

    for (int tt = 0; tt < T; tt++) {
        if (tt + 2 < T) CP_WAIT1(); else CP_WAIT0();
        __syncthreads();     // buf tt%3 visible; buf (tt+2)%3 free for staging
        if (tt + 2 < T) {
            gemm_stage_async(sm, (tt + 2) % 3, A, Bm, m0, n0, (tt + 2) * 32, K, N, tid);
            CP_COMMIT();
        }
        const float* As = sm + (tt % 3) * GEMM_STG_F;
        const float* Bs = As + 128 * 36;
#pragma unroll
        for (int ks = 0; ks < 4; ks++) {
            uint32_t bb[4][2];
#pragma unroll
            for (int nt = 0; nt < 4; nt++) {
                int col = wn * 32 + nt * 8 + g;
                bb[nt][0] = __float_as_uint(Bs[(ks * 8 + t) * 132 + col]);
                bb[nt][1] = __float_as_uint(Bs[(ks * 8 + t + 4) * 132 + col]);
            }
#pragma unroll
            for (int mt = 0; mt < 4; mt++) {
                int rb = wm * 64 + mt * 16;
                uint32_t aa[4];
                aa[0] = __float_as_uint(As[(rb + g) * 36 + ks * 8 + t]);
                aa[1] = __float_as_uint(As[(rb + g + 8) * 36 + ks * 8 + t]);
                aa[2] = __float_as_uint(As[(rb + g) * 36 + ks * 8 + t + 4]);
                aa[3] = __float_as_uint(As[(rb + g + 8) * 36 + ks * 8 + t + 4]);
#pragma unroll
                for (int nt = 0; nt < 4; nt++)
                    mma8(acc[mt][nt], aa, bb[nt]);
            }
        }
    }

    // epilogue
#pragma unroll
    for (int mt = 0; mt < 4; mt++) {
        int r0 = m0 + wm * 64 + mt * 16 + g;
        int r1 = r0 + 8;
#pragma unroll
        for (int nt = 0; nt < 4; nt++) {
            int col = n0 + wn * 32 + nt * 8 + 2 * t;
            float2 b2 = *(const float2*)(bias + col);
            if (mode == 0) {
                float2 v0 = { acc[mt][nt][0] + b2.x, acc[mt][nt][1] + b2.y };
                float2 v1 = { acc[mt][nt][2] + b2.x, acc[mt][nt][3] + b2.y };
                *(float2*)(C + (size_t)r0 * N + col) = v0;
                *(float2*)(C + (size_t)r1 * N + col) = v1;
            } else {
                // tf32-round q/k/v at write so attention needs no cvt
                float2 v0 = { tff(acc[mt][nt][0] + b2.x), tff(acc[mt][nt][1] + b2.y) };
                float2 v1 = { tff(acc[mt][nt][2] + b2.x), tff(acc[mt][nt][3] + b2.y) };
                int part = col >> 10;
                int rr   = col & 1023;
                int h    = rr >> 6;
                int hd   = rr & 63;
                float* dst = (part == 0) ? g_q : (part == 1) ? g_k : g_v;
                int b0i = r0 >> 11, s0 = r0 & 2047;
                int b1i = r1 >> 11, s1 = r1 & 2047;
                *(float2*)(dst + ((size_t)(b0i * NHEAD + h) * SEQ + s0) * HDIM + hd) = v0;
                *(float2*)(dst + ((size_t)(b1i * NHEAD + h) * SEQ + s1) * HDIM + hd) = v1;
            }
        }
    }
}

// ---------------------------------------------------------------------------
// Tensor-core causal flash attention (tf32 mma.sync), cp.async pipeline.
// CTA: 256 threads (8 warps), BM=128 (16 rows/warp), BN=64 keys/tile.
// Inputs pre-rounded; exp via MUFU ex2; P rounded at store only.
// ---------------------------------------------------------------------------
#define ATT_QF   (128 * 68)                   // 8704
#define ATT_KVF  (2 * 64 * 68)                // 8704 per stage
#define ATT_SMEM ((ATT_QF + 2 * ATT_KVF) * 4) // 104,448 B

__device__ __forceinline__ void attn_stage_kv_async(
    float* base, int s, const float* __restrict__ kbp, const float* __restrict__ vbp,
    int kb, int tid)
{
    float* Ks = base + ATT_QF + s * ATT_KVF;
    float* Vs = Ks + 64 * 68;
#pragma unroll
    for (int i = 0; i < 4; i++) {
        int f = tid + i * 256;
        int row = f >> 4, c0 = (f & 15) * 4;
        cp16(&Ks[row * 68 + c0], kbp + (size_t)(kb + row) * HDIM + c0);
        cp16(&Vs[row * 68 + c0], vbp + (size_t)(kb + row) * HDIM + c0);
    }
}

__global__ __launch_bounds__(256, 2) void attn_tc()
{
    extern __shared__ float smx[];
    float* Qs = smx;

    const int tid  = threadIdx.x;
    const int wid  = tid >> 5;
    const int lane = tid & 31;
    const int g = lane >> 2, t = lane & 3;
    const int bh = blockIdx.y;
    const int m0 = ((int)gridDim.x - 1 - (int)blockIdx.x) * 128;  // heavy first

    const float* qb  = g_q + (size_t)bh * SEQ * HDIM;
    const float* kbp = g_k + (size_t)bh * SEQ * HDIM;
    const float* vbp = g_v + (size_t)bh * SEQ * HDIM;

    const int ntile = m0 / 64 + 2;           // >= 2 always

    // prologue: Q + KV tile0 in group 0, KV tile1 in group 1
#pragma unroll
    for (int i = 0; i < 8; i++) {
        int f = tid + i * 256;
        int row = f >> 4, c0 = (f & 15) * 4;
        cp16(&Qs[row * 68 + c0], qb + (size_t)(m0 + row) * HDIM + c0);
    }
    attn_stage_kv_async(smx, 0, kbp, vbp, 0, tid);
    CP_COMMIT();
    attn_stage_kv_async(smx, 1, kbp, vbp, 64, tid);
    CP_COMMIT();
    CP_WAIT1();          // group 0 (Q + KV0) complete
    __syncthreads();

    // Q fragments (already tf32); warp's Q rows become its private P region
    uint32_t qa[8][4];
    {
        int rb = wid * 16;
#pragma unroll
        for (int ks = 0; ks < 8; ks++) {
            qa[ks][0] = __float_as_uint(Qs[(rb + g) * 68 + ks * 8 + t]);
            qa[ks][1] = __float_as_uint(Qs[(rb + g + 8) * 68 + ks * 8 + t]);
            qa[ks][2] = __float_as_uint(Qs[(rb + g) * 68 + ks * 8 + t + 4]);
            qa[ks][3] = __float_as_uint(Qs[(rb + g + 8) * 68 + ks * 8 + t + 4]);
        }
    }

    float o[8][4];
#pragma unroll
    for (int nt = 0; nt < 8; nt++)
#pragma unroll
        for (int j = 0; j < 4; j++) o[nt][j] = 0.f;
    float mlo = -1e30f, mhi = -1e30f, llo = 0.f, lhi = 0.f;

    const float SC = 0.125f * 1.44269504f;   // score scale, base-2 domain

    for (int tt = 0; tt < ntile; tt++) {
        const int kb = tt * 64;
        const float* Kc = smx + ATT_QF + (tt & 1) * ATT_KVF;
        const float* Vc = Kc + 64 * 68;

        // S = Q @ K^T  (warp: 16 x 64)
        float s[8][4];
#pragma unroll
        for (int nt = 0; nt < 8; nt++)
#pragma unroll
            for (int j = 0; j < 4; j++) s[nt][j] = 0.f;
#pragma unroll
        for (int ks = 0; ks < 8; ks++) {
#pragma unroll
            for (int nt = 0; nt < 8; nt++) {
                uint32_t bb[2];
                bb[0] = __float_as_uint(Kc[(nt * 8 + g) * 68 + ks * 8 + t]);
                bb[1] = __float_as_uint(Kc[(nt * 8 + g) * 68 + ks * 8 + t + 4]);
                mma8(s[nt], qa[ks], bb);
            }
        }

        // scale (+ causal mask near diagonal)
        const int rlo = m0 + wid * 16 + g;
        const int rhi = rlo + 8;
        if (kb + 63 > m0 + wid * 16) {
#pragma unroll
            for (int nt = 0; nt < 8; nt++) {
                int c0 = kb + nt * 8 + 2 * t;
                s[nt][0] = (c0     > rlo) ? -1e30f : s[nt][0] * SC;
                s[nt][1] = (c0 + 1 > rlo) ? -1e30f : s[nt][1] * SC;
                s[nt][2] = (c0     > rhi) ? -1e30f : s[nt][2] * SC;
                s[nt][3] = (c0 + 1 > rhi) ? -1e30f : s[nt][3] * SC;
            }
        } else {
#pragma unroll
            for (int nt = 0; nt < 8; nt++)
#pragma unroll
                for (int j = 0; j < 4; j++) s[nt][j] *= SC;
        }

        // row max (quad reduction)
        float tlo = -1e30f, thi = -1e30f;
#pragma unroll
        for (int nt = 0; nt < 8; nt++) {
            tlo = fmaxf(tlo, fmaxf(s[nt][0], s[nt][1]));
            thi = fmaxf(thi, fmaxf(s[nt][2], s[nt][3]));
        }
        tlo = fmaxf(tlo, __shfl_xor_sync(0xffffffff, tlo, 1));
        tlo = fmaxf(tlo, __shfl_xor_sync(0xffffffff, tlo, 2));
        thi = fmaxf(thi, __shfl_xor_sync(0xffffffff, thi, 1));
        thi = fmaxf(thi, __shfl_xor_sync(0xffffffff, thi, 2));

        float nmlo = fmaxf(mlo, tlo), nmhi = fmaxf(mhi, thi);
        float alo = ex2f(mlo - nmlo), ahi = ex2f(mhi - nmhi);
        mlo = nmlo; mhi = nmhi;

        // p = 2^(s-m) via MUFU, partial sums
        float slo = 0.f, shi = 0.f;
#pragma unroll
        for (int nt = 0; nt < 8; nt++) {
            s[nt][0] = ex2f(s[nt][0] - mlo);
            s[nt][1] = ex2f(s[nt][1] - mlo);
            s[nt][2] = ex2f(s[nt][2] - mhi);
            s[nt][3] = ex2f(s[nt][3] - mhi);
            slo += s[nt][0] + s[nt][1];
            shi += s[nt][2] + s[nt][3];
        }
        slo += __shfl_xor_sync(0xffffffff, slo, 1);
        slo += __shfl_xor_sync(0xffffffff, slo, 2);
        shi += __shfl_xor_sync(0xffffffff, shi, 1);
        shi += __shfl_xor_sync(0xffffffff, shi, 2);
        llo = llo * alo + slo;
        lhi = lhi * ahi + shi;

        // rescale O
#pragma unroll
        for (int nt = 0; nt < 8; nt++) {
            o[nt][0] *= alo; o[nt][1] *= alo;
            o[nt][2] *= ahi; o[nt][3] *= ahi;
        }

        // P -> warp-private 16x68 region (tf32 bits), then O += P @ V
        float* Ps = Qs + wid * (16 * 68);
#pragma unroll
        for (int nt = 0; nt < 8; nt++) {
            int c = nt * 8 + 2 * t;
            uint2 plo = { f2tf32(s[nt][0]), f2tf32(s[nt][1]) };
            uint2 phi = { f2tf32(s[nt][2]), f2tf32(s[nt][3]) };
            *(uint2*)&Ps[g * 68 + c]       = plo;
            *(uint2*)&Ps[(g + 8) * 68 + c] = phi;
        }
        __syncwarp();

#pragma unroll
        for (int ks = 0; ks < 8; ks++) {
            uint32_t aa[4];
            aa[0] = __float_as_uint(Ps[g * 68 + ks * 8 + t]);
            aa[1] = __float_as_uint(Ps[(g + 8) * 68 + ks * 8 + t]);
            aa[2] = __float_as_uint(Ps[g * 68 + ks * 8 + t + 4]);
            aa[3] = __float_as_uint(Ps[(g + 8) * 68 + ks * 8 + t + 4]);
#pragma unroll
            for (int nt = 0; nt < 8; nt++) {
                uint32_t bb[2];
                bb[0] = __float_as_uint(Vc[(ks * 8 + t) * 68 + nt * 8 + g]);
                bb[1] = __float_as_uint(Vc[(ks * 8 + t + 4) * 68 + nt * 8 + g]);
                mma8(o[nt], aa, bb);
            }
        }

        __syncthreads();   // all warps done reading KV buf (tt&1)
        if (tt + 2 < ntile) {
            attn_stage_kv_async(smx, tt & 1, kbp, vbp, (tt + 2) * 64, tid);
            CP_COMMIT();
            CP_WAIT1();
        } else {
            CP_WAIT0();
        }
        __syncthreads();
    }

    // epilogue: O /= l, tf32-round, write to ctx (feeds tf32 proj GEMM)
    const float ilo = 1.f / llo, ihi = 1.f / lhi;
    const int rlo = m0 + wid * 16 + g;
    const int rhi = rlo + 8;
    const int bidx = bh >> 4, h = bh & 15;
    float* clo = g_ctx + ((size_t)(bidx * SEQ + rlo)) * DMODEL + h * HDIM;
    float* chi = g_ctx + ((size_t)(bidx * SEQ + rhi)) * DMODEL + h * HDIM;
#pragma unroll
    for (int nt = 0; nt < 8; nt++) {
        int c = nt * 8 + 2 * t;
        float2 v0 = { tff(o[nt][0] * ilo), tff(o[nt][1] * ilo) };
        float2 v1 = { tff(o[nt][2] * ihi), tff(o[nt][3] * ihi) };
        *(float2*)(clo + c) = v0;
        *(float2*)(chi + c) = v1;
    }
}

// ---------------------------------------------------------------------------
extern "C" void kernel_launch(void* const* d_in, const int* in_sizes, int n_in,
                              void* d_out, int out_size)
{
    const float* x      = (const float*)d_in[0];   // [B,S,D]
    const float* w_qkv  = (const float*)d_in[1];   // [D, 3D]
    const float* b_qkv  = (const float*)d_in[2];   // [3D]
    const float* w_proj = (const float*)d_in[3];   // [D, D]
    const float* b_proj = (const float*)d_in[4];   // [D]
    float* out = (float*)d_out;                    // [B,S,D]

    float *xr, *wqkvr, *wprojr, *ctx;
    cudaGetSymbolAddress((void**)&xr, g_x);
    cudaGetSymbolAddress((void**)&wqkvr, g_wqkv);
    cudaGetSymbolAddress((void**)&wprojr, g_wproj);
    cudaGetSymbolAddress((void**)&ctx, g_ctx);

    cudaFuncSetAttribute(gemm_tc, cudaFuncAttributeMaxDynamicSharedMemorySize, GEMM_SMEM);
    cudaFuncSetAttribute(attn_tc, cudaFuncAttributeMaxDynamicSharedMemorySize, ATT_SMEM);

    // 0) pre-round inputs to tf32 (removes all cvt from hot loops)
    tf32_round_kernel<<<1184, 256>>>((const float4*)x, (float4*)xr,
                                     MROWS * DMODEL / 4);
    tf32_round_kernel<<<1184, 256>>>((const float4*)w_qkv, (float4*)wqkvr,
                                     DMODEL * 3 * DMODEL / 4);
    tf32_round_kernel<<<1184, 256>>>((const float4*)w_proj, (float4*)wprojr,
                                     DMODEL * DMODEL / 4);

    // 1) QKV projection -> g_q/g_k/g_v (tf32-rounded at write)
    {
        dim3 grid(3 * DMODEL / 128, MROWS / 128);  // (24, 32)
        gemm_tc<<<grid, 256, GEMM_SMEM>>>(xr, wqkvr, b_qkv, nullptr,
                                          MROWS, 3 * DMODEL, DMODEL, /*mode=*/1);
    }
    // 2) causal attention -> g_ctx (tf32-rounded at write)
    {
        dim3 grid(SEQ / 128, BH);                  // (16, 32)
        attn_tc<<<grid, 256, ATT_SMEM>>>();
    }
    // 3) output projection -> d_out (raw f32)
    {
        dim3 grid(DMODEL / 128, MROWS / 128);      // (8, 32)
        gemm_tc<<<grid, 256, GEMM_SMEM>>>(ctx, wprojr, b_proj, out,
                                          MROWS, DMODEL, DMODEL, /*mode=*/0);
    }
    (void)in_sizes; (void)n_in; (void)out_size;
}

// round 8
// speedup vs baseline: 1.2364x; 1.1261x over previous
#include <cuda_runtime.h>
#include <cstdint>

// Problem constants
#define BATCH 2
#define SEQ   2048
#define DMODEL 1024
#define NHEAD 16
#define HDIM  64
#define BH    (BATCH*NHEAD)          // 32
#define MROWS (BATCH*SEQ)            // 4096

// Scratch (device globals: allocation-free per harness rules)
__device__ float g_x[MROWS * DMODEL];          // tf32-rounded x
__device__ float g_wqkv[DMODEL * 3 * DMODEL];  // tf32-rounded w_qkv
__device__ float g_wproj[DMODEL * DMODEL];     // tf32-rounded w_proj
__device__ float g_q[BH * SEQ * HDIM];         // [bh][s][hd] (tf32-rounded)
__device__ float g_k[BH * SEQ * HDIM];
__device__ float g_v[BH * SEQ * HDIM];
__device__ float g_ctx[MROWS * DMODEL];        // [b*S+s][d] (tf32-rounded)

// ---------------------------------------------------------------------------
// helpers
// ---------------------------------------------------------------------------
__device__ __forceinline__ uint32_t f2tf32(float x) {
    uint32_t r;
    asm("cvt.rna.tf32.f32 %0, %1;" : "=r"(r) : "f"(x));
    return r;
}
__device__ __forceinline__ float tff(float x) {        // tf32-rounded, as float
    return __uint_as_float(f2tf32(x));
}
__device__ __forceinline__ float ex2f(float x) {       // 2^x via MUFU
    float r;
    asm("ex2.approx.f32 %0, %1;" : "=f"(r) : "f"(x));
    return r;
}

// async 16B copy gmem -> smem
__device__ __forceinline__ void cp16(void* smem_dst, const void* gsrc) {
    uint32_t d;
    asm("{ .reg .u64 t; cvta.to.shared.u64 t, %1; cvt.u32.u64 %0, t; }"
        : "=r"(d) : "l"(smem_dst));
    asm volatile("cp.async.cg.shared.global [%0], [%1], 16;" :: "r"(d), "l"(gsrc));
}
#define CP_COMMIT() asm volatile("cp.async.commit_group;" ::: "memory")
#define CP_WAIT1()  asm volatile("cp.async.wait_group 1;" ::: "memory")
#define CP_WAIT0()  asm volatile("cp.async.wait_group 0;" ::: "memory")

// mma.m16n8k8 tf32, D += A*B (C aliased to D)
__device__ __forceinline__ void mma8(float* d, const uint32_t* a, const uint32_t* b) {
    asm volatile(
        "mma.sync.aligned.m16n8k8.row.col.f32.tf32.tf32.f32 "
        "{%0,%1,%2,%3}, {%4,%5,%6,%7}, {%8,%9}, {%0,%1,%2,%3};\n"
        : "+f"(d[0]), "+f"(d[1]), "+f"(d[2]), "+f"(d[3])
        : "r"(a[0]), "r"(a[1]), "r"(a[2]), "r"(a[3]), "r"(b[0]), "r"(b[1]));
}

// ---------------------------------------------------------------------------
// tf32 pre-round pass (grid-stride over float4)
// ---------------------------------------------------------------------------
__global__ void tf32_round_kernel(const float4* __restrict__ in,
                                  float4* __restrict__ out, int n4)
{
    for (int i = blockIdx.x * blockDim.x + threadIdx.x; i < n4;
         i += gridDim.x * blockDim.x) {
        float4 v = in[i];
        float4 o = { tff(v.x), tff(v.y), tff(v.z), tff(v.w) };
        out[i] = o;
    }
}

// ---------------------------------------------------------------------------
// tf32 mma.sync GEMM: C[M,N] = A[M,K] @ B[K,N] + bias. Inputs pre-rounded.
// Tile 128x128x32, 256 threads, 8 warps (2m x 4n), warp tile 64x32.
// 3-stage cp.async ring, one barrier per k-tile.
// mode 0: write C raw f32 ; mode 1: scatter tf32-rounded q/k/v
// ---------------------------------------------------------------------------
#define GEMM_STG_F (128*36 + 32*132)          // 8832 floats per stage
#define GEMM_SMEM  (3 * GEMM_STG_F * 4)       // 105,984 B

__device__ __forceinline__ void gemm_stage_async(
    float* sm, int s, const float* __restrict__ A, const float* __restrict__ Bm,
    int m0, int n0, int kt, int K, int N, int tid)
{
    float* As = sm + s * GEMM_STG_F;
    float* Bs = As + 128 * 36;
#pragma unroll
    for (int i = 0; i < 4; i++) {
        int f = tid + i * 256;
        int row = f >> 3, c0 = (f & 7) * 4;
        cp16(&As[row * 36 + c0], A + (size_t)(m0 + row) * K + kt + c0);
    }
#pragma unroll
    for (int i = 0; i < 4; i++) {
        int f = tid + i * 256;
        int kr = f >> 5, c0 = (f & 31) * 4;
        cp16(&Bs[kr * 132 + c0], Bm + (size_t)(kt + kr) * N + n0 + c0);
    }
}

__global__ __launch_bounds__(256, 2) void gemm_tc(
    const float* __restrict__ A, const float* __restrict__ Bm,
    const float* __restrict__ bias, float* __restrict__ C,
    int M, int N, int K, int mode)
{
    extern __shared__ float sm[];

    const int tid  = threadIdx.x;
    const int wid  = tid >> 5;
    const int lane = tid & 31;
    const int g = lane >> 2, t = lane & 3;
    const int wm = wid >> 2, wn = wid & 3;
    const int m0 = blockIdx.y * 128;
    const int n0 = blockIdx.x * 128;

    float acc[4][4][4];
#pragma unroll
    for (int mt = 0; mt < 4; mt++)
#pragma unroll
        for (int nt = 0; nt < 4; nt++)
#pragma unroll
            for (int j = 0; j < 4; j++) acc[mt][nt][j] = 0.f;

    const int T = K / 32;   // 32
    gemm_stage_async(sm, 0, A, Bm, m0, n0, 0, K, N, tid);
    CP_COMMIT();
    gemm_stage_async(sm, 1, A, Bm, m0, n0, 32, K, N, tid);
    CP_COMMIT();

    for (int tt = 0; tt < T; tt++) {
        if (tt + 2 < T) CP_WAIT1(); else CP_WAIT0();
        __syncthreads();     // buf tt%3 visible; buf (tt+2)%3 free for staging
        if (tt + 2 < T) {
            gemm_stage_async(sm, (tt + 2) % 3, A, Bm, m0, n0, (tt + 2) * 32, K, N, tid);
            CP_COMMIT();
        }
        const float* As = sm + (tt % 3) * GEMM_STG_F;
        const float* Bs = As + 128 * 36;
#pragma unroll
        for (int ks = 0; ks < 4; ks++) {
            uint32_t bb[4][2];
#pragma unroll
            for (int nt = 0; nt < 4; nt++) {
                int col = wn * 32 + nt * 8 + g;
                bb[nt][0] = __float_as_uint(Bs[(ks * 8 + t) * 132 + col]);
                bb[nt][1] = __float_as_uint(Bs[(ks * 8 + t + 4) * 132 + col]);
            }
#pragma unroll
            for (int mt = 0; mt < 4; mt++) {
                int rb = wm * 64 + mt * 16;
                uint32_t aa[4];
                aa[0] = __float_as_uint(As[(rb + g) * 36 + ks * 8 + t]);
                aa[1] = __float_as_uint(As[(rb + g + 8) * 36 + ks * 8 + t]);
                aa[2] = __float_as_uint(As[(rb + g) * 36 + ks * 8 + t + 4]);
                aa[3] = __float_as_uint(As[(rb + g + 8) * 36 + ks * 8 + t + 4]);
#pragma unroll
                for (int nt = 0; nt < 4; nt++)
                    mma8(acc[mt][nt], aa, bb[nt]);
            }
        }
    }

    // epilogue
#pragma unroll
    for (int mt = 0; mt < 4; mt++) {
        int r0 = m0 + wm * 64 + mt * 16 + g;
        int r1 = r0 + 8;
#pragma unroll
        for (int nt = 0; nt < 4; nt++) {
            int col = n0 + wn * 32 + nt * 8 + 2 * t;
            float2 b2 = *(const float2*)(bias + col);
            if (mode == 0) {
                float2 v0 = { acc[mt][nt][0] + b2.x, acc[mt][nt][1] + b2.y };
                float2 v1 = { acc[mt][nt][2] + b2.x, acc[mt][nt][3] + b2.y };
                *(float2*)(C + (size_t)r0 * N + col) = v0;
                *(float2*)(C + (size_t)r1 * N + col) = v1;
            } else {
                float2 v0 = { tff(acc[mt][nt][0] + b2.x), tff(acc[mt][nt][1] + b2.y) };
                float2 v1 = { tff(acc[mt][nt][2] + b2.x), tff(acc[mt][nt][3] + b2.y) };
                int part = col >> 10;
                int rr   = col & 1023;
                int h    = rr >> 6;
                int hd   = rr & 63;
                float* dst = (part == 0) ? g_q : (part == 1) ? g_k : g_v;
                int b0i = r0 >> 11, s0 = r0 & 2047;
                int b1i = r1 >> 11, s1 = r1 & 2047;
                *(float2*)(dst + ((size_t)(b0i * NHEAD + h) * SEQ + s0) * HDIM + hd) = v0;
                *(float2*)(dst + ((size_t)(b1i * NHEAD + h) * SEQ + s1) * HDIM + hd) = v1;
            }
        }
    }
}

// ---------------------------------------------------------------------------
// Tensor-core causal flash attention (tf32 mma.sync), cp.async pipeline.
// CTA: 128 threads (4 warps), BM=128, 32 rows/warp (2 m16 halves), BN=64.
// Each K/V fragment pair feeds TWO mma (both m-halves): smem-op/HMMA = 1.
// ---------------------------------------------------------------------------
#define ATT_QF   (128 * 68)                   // 8704 floats (reused as P)
#define ATT_KVF  (2 * 64 * 68)                // 8704 per stage
#define ATT_SMEM ((ATT_QF + 2 * ATT_KVF) * 4) // 104,448 B

__device__ __forceinline__ void attn_stage_kv_async(
    float* base, int s, const float* __restrict__ kbp, const float* __restrict__ vbp,
    int kb, int tid)
{
    float* Ks = base + ATT_QF + s * ATT_KVF;
    float* Vs = Ks + 64 * 68;
#pragma unroll
    for (int i = 0; i < 8; i++) {
        int f = tid + i * 128;               // 0..1023
        int row = f >> 4, c0 = (f & 15) * 4;
        cp16(&Ks[row * 68 + c0], kbp + (size_t)(kb + row) * HDIM + c0);
        cp16(&Vs[row * 68 + c0], vbp + (size_t)(kb + row) * HDIM + c0);
    }
}

__global__ __launch_bounds__(128, 2) void attn_tc()
{
    extern __shared__ float smx[];
    float* Qs = smx;

    const int tid  = threadIdx.x;
    const int wid  = tid >> 5;
    const int lane = tid & 31;
    const int g = lane >> 2, t = lane & 3;
    const int bh = blockIdx.y;
    const int m0 = ((int)gridDim.x - 1 - (int)blockIdx.x) * 128;  // heavy first

    const float* qb  = g_q + (size_t)bh * SEQ * HDIM;
    const float* kbp = g_k + (size_t)bh * SEQ * HDIM;
    const float* vbp = g_v + (size_t)bh * SEQ * HDIM;

    const int ntile = m0 / 64 + 2;           // >= 2 always
    const int rb = wid * 32;                 // warp's row base within tile

    // prologue: Q + KV tile0 in group 0, KV tile1 in group 1
#pragma unroll
    for (int i = 0; i < 16; i++) {
        int f = tid + i * 128;
        int row = f >> 4, c0 = (f & 15) * 4;
        cp16(&Qs[row * 68 + c0], qb + (size_t)(m0 + row) * HDIM + c0);
    }
    attn_stage_kv_async(smx, 0, kbp, vbp, 0, tid);
    CP_COMMIT();
    attn_stage_kv_async(smx, 1, kbp, vbp, 64, tid);
    CP_COMMIT();
    CP_WAIT1();          // group 0 (Q + KV0) complete
    __syncthreads();

    // Q fragments (already tf32), both m16 halves
    uint32_t qa[2][8][4];
#pragma unroll
    for (int mh = 0; mh < 2; mh++) {
        int r = rb + mh * 16;
#pragma unroll
        for (int ks = 0; ks < 8; ks++) {
            qa[mh][ks][0] = __float_as_uint(Qs[(r + g) * 68 + ks * 8 + t]);
            qa[mh][ks][1] = __float_as_uint(Qs[(r + g + 8) * 68 + ks * 8 + t]);
            qa[mh][ks][2] = __float_as_uint(Qs[(r + g) * 68 + ks * 8 + t + 4]);
            qa[mh][ks][3] = __float_as_uint(Qs[(r + g + 8) * 68 + ks * 8 + t + 4]);
        }
    }

    float o[2][8][4];
#pragma unroll
    for (int mh = 0; mh < 2; mh++)
#pragma unroll
        for (int nt = 0; nt < 8; nt++)
#pragma unroll
            for (int j = 0; j < 4; j++) o[mh][nt][j] = 0.f;
    float mm[2][2] = { {-1e30f, -1e30f}, {-1e30f, -1e30f} };   // [mh][lo/hi]
    float ll[2][2] = { {0.f, 0.f}, {0.f, 0.f} };

    const float SC = 0.125f * 1.44269504f;   // score scale, base-2 domain

    for (int tt = 0; tt < ntile; tt++) {
        const int kb = tt * 64;
        const float* Kc = smx + ATT_QF + (tt & 1) * ATT_KVF;
        const float* Vc = Kc + 64 * 68;

        // skip tiles fully above the causal diagonal for this warp
        if (kb <= m0 + rb + 31) {
            // S = Q @ K^T  (warp: 32 x 64; K frag shared by both halves)
            float s[2][8][4];
#pragma unroll
            for (int mh = 0; mh < 2; mh++)
#pragma unroll
                for (int nt = 0; nt < 8; nt++)
#pragma unroll
                    for (int j = 0; j < 4; j++) s[mh][nt][j] = 0.f;
#pragma unroll
            for (int ks = 0; ks < 8; ks++) {
#pragma unroll
                for (int nt = 0; nt < 8; nt++) {
                    uint32_t bb[2];
                    bb[0] = __float_as_uint(Kc[(nt * 8 + g) * 68 + ks * 8 + t]);
                    bb[1] = __float_as_uint(Kc[(nt * 8 + g) * 68 + ks * 8 + t + 4]);
                    mma8(s[0][nt], qa[0][ks], bb);
                    mma8(s[1][nt], qa[1][ks], bb);
                }
            }

            // scale (+ causal mask near diagonal), softmax per m-half
#pragma unroll
            for (int mh = 0; mh < 2; mh++) {
                const int rlo = m0 + rb + mh * 16 + g;
                const int rhi = rlo + 8;
                if (kb + 63 > m0 + rb + mh * 16) {
#pragma unroll
                    for (int nt = 0; nt < 8; nt++) {
                        int c0 = kb + nt * 8 + 2 * t;
                        s[mh][nt][0] = (c0     > rlo) ? -1e30f : s[mh][nt][0] * SC;
                        s[mh][nt][1] = (c0 + 1 > rlo) ? -1e30f : s[mh][nt][1] * SC;
                        s[mh][nt][2] = (c0     > rhi) ? -1e30f : s[mh][nt][2] * SC;
                        s[mh][nt][3] = (c0 + 1 > rhi) ? -1e30f : s[mh][nt][3] * SC;
                    }
                } else {
#pragma unroll
                    for (int nt = 0; nt < 8; nt++)
#pragma unroll
                        for (int j = 0; j < 4; j++) s[mh][nt][j] *= SC;
                }

                float tlo = -1e30f, thi = -1e30f;
#pragma unroll
                for (int nt = 0; nt < 8; nt++) {
                    tlo = fmaxf(tlo, fmaxf(s[mh][nt][0], s[mh][nt][1]));
                    thi = fmaxf(thi, fmaxf(s[mh][nt][2], s[mh][nt][3]));
                }
                tlo = fmaxf(tlo, __shfl_xor_sync(0xffffffff, tlo, 1));
                tlo = fmaxf(tlo, __shfl_xor_sync(0xffffffff, tlo, 2));
                thi = fmaxf(thi, __shfl_xor_sync(0xffffffff, thi, 1));
                thi = fmaxf(thi, __shfl_xor_sync(0xffffffff, thi, 2));

                float nmlo = fmaxf(mm[mh][0], tlo), nmhi = fmaxf(mm[mh][1], thi);
                float alo = ex2f(mm[mh][0] - nmlo), ahi = ex2f(mm[mh][1] - nmhi);
                mm[mh][0] = nmlo; mm[mh][1] = nmhi;

                float slo = 0.f, shi = 0.f;
#pragma unroll
                for (int nt = 0; nt < 8; nt++) {
                    s[mh][nt][0] = ex2f(s[mh][nt][0] - nmlo);
                    s[mh][nt][1] = ex2f(s[mh][nt][1] - nmlo);
                    s[mh][nt][2] = ex2f(s[mh][nt][2] - nmhi);
                    s[mh][nt][3] = ex2f(s[mh][nt][3] - nmhi);
                    slo += s[mh][nt][0] + s[mh][nt][1];
                    shi += s[mh][nt][2] + s[mh][nt][3];
                }
                slo += __shfl_xor_sync(0xffffffff, slo, 1);
                slo += __shfl_xor_sync(0xffffffff, slo, 2);
                shi += __shfl_xor_sync(0xffffffff, shi, 1);
                shi += __shfl_xor_sync(0xffffffff, shi, 2);
                ll[mh][0] = ll[mh][0] * alo + slo;
                ll[mh][1] = ll[mh][1] * ahi + shi;

#pragma unroll
                for (int nt = 0; nt < 8; nt++) {
                    o[mh][nt][0] *= alo; o[mh][nt][1] *= alo;
                    o[mh][nt][2] *= ahi; o[mh][nt][3] *= ahi;
                }

                // P -> warp-private region (tf32 bits)
                float* Ps = Qs + wid * (32 * 68) + mh * (16 * 68);
#pragma unroll
                for (int nt = 0; nt < 8; nt++) {
                    int c = nt * 8 + 2 * t;
                    uint2 plo = { f2tf32(s[mh][nt][0]), f2tf32(s[mh][nt][1]) };
                    uint2 phi = { f2tf32(s[mh][nt][2]), f2tf32(s[mh][nt][3]) };
                    *(uint2*)&Ps[g * 68 + c]       = plo;
                    *(uint2*)&Ps[(g + 8) * 68 + c] = phi;
                }
            }
            __syncwarp();

            // O += P @ V  (V frag shared by both halves)
            const float* P0 = Qs + wid * (32 * 68);
            const float* P1 = P0 + 16 * 68;
#pragma unroll
            for (int ks = 0; ks < 8; ks++) {
                uint32_t a0[4], a1[4];
                a0[0] = __float_as_uint(P0[g * 68 + ks * 8 + t]);
                a0[1] = __float_as_uint(P0[(g + 8) * 68 + ks * 8 + t]);
                a0[2] = __float_as_uint(P0[g * 68 + ks * 8 + t + 4]);
                a0[3] = __float_as_uint(P0[(g + 8) * 68 + ks * 8 + t + 4]);
                a1[0] = __float_as_uint(P1[g * 68 + ks * 8 + t]);
                a1[1] = __float_as_uint(P1[(g + 8) * 68 + ks * 8 + t]);
                a1[2] = __float_as_uint(P1[g * 68 + ks * 8 + t + 4]);
                a1[3] = __float_as_uint(P1[(g + 8) * 68 + ks * 8 + t + 4]);
#pragma unroll
                for (int nt = 0; nt < 8; nt++) {
                    uint32_t bb[2];
                    bb[0] = __float_as_uint(Vc[(ks * 8 + t) * 68 + nt * 8 + g]);
                    bb[1] = __float_as_uint(Vc[(ks * 8 + t + 4) * 68 + nt * 8 + g]);
                    mma8(o[0][nt], a0, bb);
                    mma8(o[1][nt], a1, bb);
                }
            }
            __syncwarp();
        }

        __syncthreads();   // all warps done reading KV buf (tt&1)
        if (tt + 2 < ntile) {
            attn_stage_kv_async(smx, tt & 1, kbp, vbp, (tt + 2) * 64, tid);
            CP_COMMIT();
            CP_WAIT1();
        } else {
            CP_WAIT0();
        }
        __syncthreads();
    }

    // epilogue: O /= l, tf32-round, write to ctx (feeds tf32 proj GEMM)
    const int bidx = bh >> 4, h = bh & 15;
#pragma unroll
    for (int mh = 0; mh < 2; mh++) {
        const float ilo = 1.f / ll[mh][0], ihi = 1.f / ll[mh][1];
        const int rlo = m0 + rb + mh * 16 + g;
        const int rhi = rlo + 8;
        float* clo = g_ctx + ((size_t)(bidx * SEQ + rlo)) * DMODEL + h * HDIM;
        float* chi = g_ctx + ((size_t)(bidx * SEQ + rhi)) * DMODEL + h * HDIM;
#pragma unroll
        for (int nt = 0; nt < 8; nt++) {
            int c = nt * 8 + 2 * t;
            float2 v0 = { tff(o[mh][nt][0] * ilo), tff(o[mh][nt][1] * ilo) };
            float2 v1 = { tff(o[mh][nt][2] * ihi), tff(o[mh][nt][3] * ihi) };
            *(float2*)(clo + c) = v0;
            *(float2*)(chi + c) = v1;
        }
    }
}

// ---------------------------------------------------------------------------
extern "C" void kernel_launch(void* const* d_in, const int* in_sizes, int n_in,
                              void* d_out, int out_size)
{
    const float* x      = (const float*)d_in[0];   // [B,S,D]
    const float* w_qkv  = (const float*)d_in[1];   // [D, 3D]
    const float* b_qkv  = (const float*)d_in[2];   // [3D]
    const float* w_proj = (const float*)d_in[3];   // [D, D]
    const float* b_proj = (const float*)d_in[4];   // [D]
    float* out = (float*)d_out;                    // [B,S,D]

    float *xr, *wqkvr, *wprojr, *ctx;
    cudaGetSymbolAddress((void**)&xr, g_x);
    cudaGetSymbolAddress((void**)&wqkvr, g_wqkv);
    cudaGetSymbolAddress((void**)&wprojr, g_wproj);
    cudaGetSymbolAddress((void**)&ctx, g_ctx);

    cudaFuncSetAttribute(gemm_tc, cudaFuncAttributeMaxDynamicSharedMemorySize, GEMM_SMEM);
    cudaFuncSetAttribute(attn_tc, cudaFuncAttributeMaxDynamicSharedMemorySize, ATT_SMEM);

    // 0) pre-round inputs to tf32
    tf32_round_kernel<<<1184, 256>>>((const float4*)x, (float4*)xr,
                                     MROWS * DMODEL / 4);
    tf32_round_kernel<<<1184, 256>>>((const float4*)w_qkv, (float4*)wqkvr,
                                     DMODEL * 3 * DMODEL / 4);
    tf32_round_kernel<<<1184, 256>>>((const float4*)w_proj, (float4*)wprojr,
                                     DMODEL * DMODEL / 4);

    // 1) QKV projection -> g_q/g_k/g_v (tf32-rounded at write)
    {
        dim3 grid(3 * DMODEL / 128, MROWS / 128);  // (24, 32)
        gemm_tc<<<grid, 256, GEMM_SMEM>>>(xr, wqkvr, b_qkv, nullptr,
                                          MROWS, 3 * DMODEL, DMODEL, /*mode=*/1);
    }
    // 2) causal attention -> g_ctx (tf32-rounded at write)
    {
        dim3 grid(SEQ / 128, BH);                  // (16, 32)
        attn_tc<<<grid, 128, ATT_SMEM>>>();
    }
    // 3) output projection -> d_out (raw f32)
    {
        dim3 grid(DMODEL / 128, MROWS / 128);      // (8, 32)
        gemm_tc<<<grid, 256, GEMM_SMEM>>>(ctx, wprojr, b_proj, out,
                                          MROWS, DMODEL, DMODEL, /*mode=*/0);
    }
    (void)in_sizes; (void)n_in; (void)out_size;
}

// round 9
// speedup vs baseline: 2.3664x; 1.9140x over previous
#include <cuda_runtime.h>
#include <cuda_fp16.h>
#include <cstdint>

// Problem constants
#define BATCH 2
#define SEQ   2048
#define DMODEL 1024
#define NHEAD 16
#define HDIM  64
#define BH    (BATCH*NHEAD)          // 32
#define MROWS (BATCH*SEQ)            // 4096

// Scratch (device globals: allocation-free per harness rules)
__device__ __half g_x[MROWS * DMODEL];
__device__ __half g_wqkv[DMODEL * 3 * DMODEL];
__device__ __half g_wproj[DMODEL * DMODEL];
__device__ __half g_q[BH * SEQ * HDIM];        // [bh][s][hd]
__device__ __half g_k[BH * SEQ * HDIM];
__device__ __half g_v[BH * SEQ * HDIM];
__device__ __half g_ctx[MROWS * DMODEL];       // [b*S+s][d]

// ---------------------------------------------------------------------------
// helpers
// ---------------------------------------------------------------------------
__device__ __forceinline__ uint32_t cvt2h(float lo, float hi) {  // pack f16x2
    uint32_t d;
    asm("cvt.rn.f16x2.f32 %0, %1, %2;" : "=r"(d) : "f"(hi), "f"(lo));
    return d;
}
__device__ __forceinline__ float ex2f(float x) {       // 2^x via MUFU
    float r;
    asm("ex2.approx.f32 %0, %1;" : "=f"(r) : "f"(x));
    return r;
}
__device__ __forceinline__ uint32_t smaddr(const void* p) {
    uint32_t a;
    asm("{ .reg .u64 t; cvta.to.shared.u64 t, %1; cvt.u32.u64 %0, t; }"
        : "=r"(a) : "l"(p));
    return a;
}

// async 16B copy gmem -> smem
__device__ __forceinline__ void cp16(void* smem_dst, const void* gsrc) {
    uint32_t d = smaddr(smem_dst);
    asm volatile("cp.async.cg.shared.global [%0], [%1], 16;" :: "r"(d), "l"(gsrc));
}
#define CP_COMMIT() asm volatile("cp.async.commit_group;" ::: "memory")
#define CP_WAIT1()  asm volatile("cp.async.wait_group 1;" ::: "memory")
#define CP_WAIT0()  asm volatile("cp.async.wait_group 0;" ::: "memory")

__device__ __forceinline__ void ldm4(uint32_t* r, uint32_t a) {
    asm volatile("ldmatrix.sync.aligned.m8n8.x4.shared.b16 {%0,%1,%2,%3}, [%4];"
        : "=r"(r[0]), "=r"(r[1]), "=r"(r[2]), "=r"(r[3]) : "r"(a));
}
__device__ __forceinline__ void ldm4t(uint32_t* r, uint32_t a) {
    asm volatile("ldmatrix.sync.aligned.m8n8.x4.trans.shared.b16 {%0,%1,%2,%3}, [%4];"
        : "=r"(r[0]), "=r"(r[1]), "=r"(r[2]), "=r"(r[3]) : "r"(a));
}

// mma m16n8k16 f16 inputs, f32 accum; D += A*B (C aliased to D)
__device__ __forceinline__ void mma16(float* d, const uint32_t* a, const uint32_t* b) {
    asm volatile(
        "mma.sync.aligned.m16n8k16.row.col.f32.f16.f16.f32 "
        "{%0,%1,%2,%3}, {%4,%5,%6,%7}, {%8,%9}, {%0,%1,%2,%3};\n"
        : "+f"(d[0]), "+f"(d[1]), "+f"(d[2]), "+f"(d[3])
        : "r"(a[0]), "r"(a[1]), "r"(a[2]), "r"(a[3]), "r"(b[0]), "r"(b[1]));
}

// ---------------------------------------------------------------------------
// f32 -> f16 pre-convert pass (grid-stride over float4)
// ---------------------------------------------------------------------------
__global__ void to_half_kernel(const float4* __restrict__ in,
                               uint2* __restrict__ out, int n4)
{
    for (int i = blockIdx.x * blockDim.x + threadIdx.x; i < n4;
         i += gridDim.x * blockDim.x) {
        float4 v = in[i];
        uint2 o = { cvt2h(v.x, v.y), cvt2h(v.z, v.w) };
        out[i] = o;
    }
}

// ---------------------------------------------------------------------------
// fp16 mma.sync GEMM: C[M,N] = A[M,K] @ B[K,N] + bias (f32 accum).
// Tile 128x128x32, 256 threads, 8 warps (2m x 4n), warp tile 64x32.
// 3-stage cp.async ring; fragments via ldmatrix.
// mode 0: write C f32 ; mode 1: scatter f16 q/k/v (QKV head layout)
// ---------------------------------------------------------------------------
#define GA_ST 40                               // A row stride (halfs)
#define GB_ST 136                              // B row stride (halfs)
#define G_STGH (128*GA_ST + 32*GB_ST)          // 9472 halfs per stage
#define GEMM_SMEM (3 * G_STGH * 2)             // 56,832 B

__device__ __forceinline__ void gemm_stage_async(
    __half* sm, int s, const __half* __restrict__ A, const __half* __restrict__ Bm,
    int m0, int n0, int kt, int K, int N, int tid)
{
    __half* As = sm + s * G_STGH;
    __half* Bs = As + 128 * GA_ST;
#pragma unroll
    for (int i = 0; i < 2; i++) {              // A: 512 granules of 8 halfs
        int f = tid + i * 256;
        int row = f >> 2, c0 = (f & 3) * 8;
        cp16(&As[row * GA_ST + c0], A + (size_t)(m0 + row) * K + kt + c0);
    }
#pragma unroll
    for (int i = 0; i < 2; i++) {              // B: 512 granules
        int f = tid + i * 256;
        int row = f >> 4, c0 = (f & 15) * 8;
        cp16(&Bs[row * GB_ST + c0], Bm + (size_t)(kt + row) * N + n0 + c0);
    }
}

__global__ __launch_bounds__(256, 2) void gemm_tc(
    const __half* __restrict__ A, const __half* __restrict__ Bm,
    const float* __restrict__ bias, float* __restrict__ C,
    int M, int N, int K, int mode)
{
    extern __shared__ __half smh[];

    const int tid  = threadIdx.x;
    const int wid  = tid >> 5;
    const int lane = tid & 31;
    const int g = lane >> 2, t = lane & 3;
    const int wm = wid >> 2, wn = wid & 3;
    const int m0 = blockIdx.y * 128;
    const int n0 = blockIdx.x * 128;

    // lane-dependent ldmatrix offsets (halfs)
    const int aLane = ((lane & 7) + ((lane >> 3) & 1) * 8) * GA_ST + (lane >> 4) * 8;
    const int bLane = ((lane & 7) + ((lane >> 3) & 1) * 8) * GB_ST + (lane >> 4) * 8;

    float acc[4][4][4];
#pragma unroll
    for (int mt = 0; mt < 4; mt++)
#pragma unroll
        for (int nt = 0; nt < 4; nt++)
#pragma unroll
            for (int j = 0; j < 4; j++) acc[mt][nt][j] = 0.f;

    const int T = K / 32;   // 32
    gemm_stage_async(smh, 0, A, Bm, m0, n0, 0, K, N, tid);
    CP_COMMIT();
    gemm_stage_async(smh, 1, A, Bm, m0, n0, 32, K, N, tid);
    CP_COMMIT();

    for (int tt = 0; tt < T; tt++) {
        if (tt + 2 < T) CP_WAIT1(); else CP_WAIT0();
        __syncthreads();
        if (tt + 2 < T) {
            gemm_stage_async(smh, (tt + 2) % 3, A, Bm, m0, n0, (tt + 2) * 32, K, N, tid);
            CP_COMMIT();
        }
        const __half* As = smh + (tt % 3) * G_STGH;
        const __half* Bs = As + 128 * GA_ST;
        const uint32_t sa = smaddr(As);
        const uint32_t sb = smaddr(Bs);
#pragma unroll
        for (int kk = 0; kk < 2; kk++) {
            uint32_t av[4][4];
#pragma unroll
            for (int mt = 0; mt < 4; mt++)
                ldm4(av[mt], sa + 2 * ((wm * 64 + mt * 16) * GA_ST + kk * 16 + aLane));
            uint32_t bv[4][4];                 // [pair][4 regs]: nt=2p (r0,r1), nt=2p+1 (r2,r3)
#pragma unroll
            for (int p = 0; p < 2; p++)
                ldm4t(bv[p], sb + 2 * (kk * 16 * GB_ST + wn * 32 + p * 16 + bLane));
#pragma unroll
            for (int mt = 0; mt < 4; mt++)
#pragma unroll
                for (int p = 0; p < 2; p++) {
                    mma16(acc[mt][2 * p],     av[mt], &bv[p][0]);
                    mma16(acc[mt][2 * p + 1], av[mt], &bv[p][2]);
                }
        }
    }

    // epilogue
#pragma unroll
    for (int mt = 0; mt < 4; mt++) {
        int r0 = m0 + wm * 64 + mt * 16 + g;
        int r1 = r0 + 8;
#pragma unroll
        for (int nt = 0; nt < 4; nt++) {
            int col = n0 + wn * 32 + nt * 8 + 2 * t;
            float2 b2 = *(const float2*)(bias + col);
            if (mode == 0) {
                float2 v0 = { acc[mt][nt][0] + b2.x, acc[mt][nt][1] + b2.y };
                float2 v1 = { acc[mt][nt][2] + b2.x, acc[mt][nt][3] + b2.y };
                *(float2*)(C + (size_t)r0 * N + col) = v0;
                *(float2*)(C + (size_t)r1 * N + col) = v1;
            } else {
                uint32_t h0 = cvt2h(acc[mt][nt][0] + b2.x, acc[mt][nt][1] + b2.y);
                uint32_t h1 = cvt2h(acc[mt][nt][2] + b2.x, acc[mt][nt][3] + b2.y);
                int part = col >> 10;
                int rr   = col & 1023;
                int h    = rr >> 6;
                int hd   = rr & 63;
                __half* dst = (part == 0) ? g_q : (part == 1) ? g_k : g_v;
                int b0i = r0 >> 11, s0 = r0 & 2047;
                int b1i = r1 >> 11, s1 = r1 & 2047;
                *(uint32_t*)(dst + ((size_t)(b0i * NHEAD + h) * SEQ + s0) * HDIM + hd) = h0;
                *(uint32_t*)(dst + ((size_t)(b1i * NHEAD + h) * SEQ + s1) * HDIM + hd) = h1;
            }
        }
    }
}

// ---------------------------------------------------------------------------
// fp16 tensor-core causal flash attention.
// CTA: 128 threads (4 warps), BM=128, 32 rows/warp (2 m16 halves), BN=64.
// Fragments via ldmatrix; P converted in-register (no smem round-trip).
// ---------------------------------------------------------------------------
#define AQ_ST 72                               // row stride (halfs)
#define ATT_QH  (128 * AQ_ST)                  // Q tile halfs
#define ATT_KVH (2 * 64 * AQ_ST)               // K+V per stage halfs
#define ATT_SMEM ((ATT_QH + 2 * ATT_KVH) * 2)  // 55,296 B

__device__ __forceinline__ void attn_stage_kv_async(
    __half* base, int s, const __half* __restrict__ kbp, const __half* __restrict__ vbp,
    int kb, int tid)
{
    __half* Ks = base + ATT_QH + s * ATT_KVH;
    __half* Vs = Ks + 64 * AQ_ST;
#pragma unroll
    for (int i = 0; i < 4; i++) {              // 512 granules each
        int f = tid + i * 128;
        int row = f >> 3, c0 = (f & 7) * 8;
        cp16(&Ks[row * AQ_ST + c0], kbp + (size_t)(kb + row) * HDIM + c0);
        cp16(&Vs[row * AQ_ST + c0], vbp + (size_t)(kb + row) * HDIM + c0);
    }
}

__global__ __launch_bounds__(128, 2) void attn_tc()
{
    extern __shared__ __half smh[];
    __half* Qs = smh;

    const int tid  = threadIdx.x;
    const int wid  = tid >> 5;
    const int lane = tid & 31;
    const int g = lane >> 2, t = lane & 3;
    const int bh = blockIdx.y;
    const int m0 = ((int)gridDim.x - 1 - (int)blockIdx.x) * 128;  // heavy first

    const __half* qb  = g_q + (size_t)bh * SEQ * HDIM;
    const __half* kbp = g_k + (size_t)bh * SEQ * HDIM;
    const __half* vbp = g_v + (size_t)bh * SEQ * HDIM;

    const int ntile = m0 / 64 + 2;
    const int rb = wid * 32;

    // lane-dependent ldmatrix offsets (halfs)
    const int qLane = ((lane & 7) + ((lane >> 3) & 1) * 8) * AQ_ST + (lane >> 4) * 8;
    const int kLane = ((lane & 7) + (lane >> 4) * 8) * AQ_ST + ((lane >> 3) & 1) * 8;
    const int vLane = qLane;   // same form (trans load)

    // prologue: Q + KV tile0 in group 0, KV tile1 in group 1
#pragma unroll
    for (int i = 0; i < 8; i++) {
        int f = tid + i * 128;
        int row = f >> 3, c0 = (f & 7) * 8;
        cp16(&Qs[row * AQ_ST + c0], qb + (size_t)(m0 + row) * HDIM + c0);
    }
    attn_stage_kv_async(smh, 0, kbp, vbp, 0, tid);
    CP_COMMIT();
    attn_stage_kv_async(smh, 1, kbp, vbp, 64, tid);
    CP_COMMIT();
    CP_WAIT1();
    __syncthreads();

    // Q fragments: [mh][kk][4]
    uint32_t qa[2][4][4];
    {
        const uint32_t sq = smaddr(Qs);
#pragma unroll
        for (int mh = 0; mh < 2; mh++)
#pragma unroll
            for (int kk = 0; kk < 4; kk++)
                ldm4(qa[mh][kk], sq + 2 * ((rb + mh * 16) * AQ_ST + kk * 16 + qLane));
    }

    float o[2][8][4];
#pragma unroll
    for (int mh = 0; mh < 2; mh++)
#pragma unroll
        for (int nt = 0; nt < 8; nt++)
#pragma unroll
            for (int j = 0; j < 4; j++) o[mh][nt][j] = 0.f;
    float mm[2][2] = { {-1e30f, -1e30f}, {-1e30f, -1e30f} };
    float ll[2][2] = { {0.f, 0.f}, {0.f, 0.f} };

    const float SC = 0.125f * 1.44269504f;     // score scale, base-2 domain

    for (int tt = 0; tt < ntile; tt++) {
        const int kb = tt * 64;
        const __half* Kc = smh + ATT_QH + (tt & 1) * ATT_KVH;
        const __half* Vc = Kc + 64 * AQ_ST;

        if (kb <= m0 + rb + 31) {
            const uint32_t sk = smaddr(Kc);
            const uint32_t sv = smaddr(Vc);

            // S = Q @ K^T (warp: 32 x 64)
            float s[2][8][4];
#pragma unroll
            for (int mh = 0; mh < 2; mh++)
#pragma unroll
                for (int nt = 0; nt < 8; nt++)
#pragma unroll
                    for (int j = 0; j < 4; j++) s[mh][nt][j] = 0.f;
#pragma unroll
            for (int kk = 0; kk < 4; kk++) {
#pragma unroll
                for (int p = 0; p < 4; p++) {
                    uint32_t r[4];
                    ldm4(r, sk + 2 * (p * 16 * AQ_ST + kk * 16 + kLane));
                    mma16(s[0][2 * p],     qa[0][kk], &r[0]);
                    mma16(s[0][2 * p + 1], qa[0][kk], &r[2]);
                    mma16(s[1][2 * p],     qa[1][kk], &r[0]);
                    mma16(s[1][2 * p + 1], qa[1][kk], &r[2]);
                }
            }

            // softmax per m-half
#pragma unroll
            for (int mh = 0; mh < 2; mh++) {
                const int rlo = m0 + rb + mh * 16 + g;
                const int rhi = rlo + 8;
                if (kb + 63 > m0 + rb + mh * 16) {
#pragma unroll
                    for (int nt = 0; nt < 8; nt++) {
                        int c0 = kb + nt * 8 + 2 * t;
                        s[mh][nt][0] = (c0     > rlo) ? -1e30f : s[mh][nt][0] * SC;
                        s[mh][nt][1] = (c0 + 1 > rlo) ? -1e30f : s[mh][nt][1] * SC;
                        s[mh][nt][2] = (c0     > rhi) ? -1e30f : s[mh][nt][2] * SC;
                        s[mh][nt][3] = (c0 + 1 > rhi) ? -1e30f : s[mh][nt][3] * SC;
                    }
                } else {
#pragma unroll
                    for (int nt = 0; nt < 8; nt++)
#pragma unroll
                        for (int j = 0; j < 4; j++) s[mh][nt][j] *= SC;
                }

                float tlo = -1e30f, thi = -1e30f;
#pragma unroll
                for (int nt = 0; nt < 8; nt++) {
                    tlo = fmaxf(tlo, fmaxf(s[mh][nt][0], s[mh][nt][1]));
                    thi = fmaxf(thi, fmaxf(s[mh][nt][2], s[mh][nt][3]));
                }
                tlo = fmaxf(tlo, __shfl_xor_sync(0xffffffff, tlo, 1));
                tlo = fmaxf(tlo, __shfl_xor_sync(0xffffffff, tlo, 2));
                thi = fmaxf(thi, __shfl_xor_sync(0xffffffff, thi, 1));
                thi = fmaxf(thi, __shfl_xor_sync(0xffffffff, thi, 2));

                float nmlo = fmaxf(mm[mh][0], tlo), nmhi = fmaxf(mm[mh][1], thi);
                float alo = ex2f(mm[mh][0] - nmlo), ahi = ex2f(mm[mh][1] - nmhi);
                mm[mh][0] = nmlo; mm[mh][1] = nmhi;

                float slo = 0.f, shi = 0.f;
#pragma unroll
                for (int nt = 0; nt < 8; nt++) {
                    s[mh][nt][0] = ex2f(s[mh][nt][0] - nmlo);
                    s[mh][nt][1] = ex2f(s[mh][nt][1] - nmlo);
                    s[mh][nt][2] = ex2f(s[mh][nt][2] - nmhi);
                    s[mh][nt][3] = ex2f(s[mh][nt][3] - nmhi);
                    slo += s[mh][nt][0] + s[mh][nt][1];
                    shi += s[mh][nt][2] + s[mh][nt][3];
                }
                slo += __shfl_xor_sync(0xffffffff, slo, 1);
                slo += __shfl_xor_sync(0xffffffff, slo, 2);
                shi += __shfl_xor_sync(0xffffffff, shi, 1);
                shi += __shfl_xor_sync(0xffffffff, shi, 2);
                ll[mh][0] = ll[mh][0] * alo + slo;
                ll[mh][1] = ll[mh][1] * ahi + shi;

#pragma unroll
                for (int nt = 0; nt < 8; nt++) {
                    o[mh][nt][0] *= alo; o[mh][nt][1] *= alo;
                    o[mh][nt][2] *= ahi; o[mh][nt][3] *= ahi;
                }
            }

            // O += P @ V  (P converted in-register to A-fragments)
#pragma unroll
            for (int kk = 0; kk < 4; kk++) {
                uint32_t pa0[4], pa1[4];
                pa0[0] = cvt2h(s[0][2*kk][0],   s[0][2*kk][1]);
                pa0[1] = cvt2h(s[0][2*kk][2],   s[0][2*kk][3]);
                pa0[2] = cvt2h(s[0][2*kk+1][0], s[0][2*kk+1][1]);
                pa0[3] = cvt2h(s[0][2*kk+1][2], s[0][2*kk+1][3]);
                pa1[0] = cvt2h(s[1][2*kk][0],   s[1][2*kk][1]);
                pa1[1] = cvt2h(s[1][2*kk][2],   s[1][2*kk][3]);
                pa1[2] = cvt2h(s[1][2*kk+1][0], s[1][2*kk+1][1]);
                pa1[3] = cvt2h(s[1][2*kk+1][2], s[1][2*kk+1][3]);
#pragma unroll
                for (int p = 0; p < 4; p++) {
                    uint32_t r[4];
                    ldm4t(r, sv + 2 * (kk * 16 * AQ_ST + p * 16 + vLane));
                    mma16(o[0][2 * p],     pa0, &r[0]);
                    mma16(o[0][2 * p + 1], pa0, &r[2]);
                    mma16(o[1][2 * p],     pa1, &r[0]);
                    mma16(o[1][2 * p + 1], pa1, &r[2]);
                }
            }
        }

        __syncthreads();
        if (tt + 2 < ntile) {
            attn_stage_kv_async(smh, tt & 1, kbp, vbp, (tt + 2) * 64, tid);
            CP_COMMIT();
            CP_WAIT1();
        } else {
            CP_WAIT0();
        }
        __syncthreads();
    }

    // epilogue: O /= l, f16, write to ctx (feeds fp16 proj GEMM)
    const int bidx = bh >> 4, h = bh & 15;
#pragma unroll
    for (int mh = 0; mh < 2; mh++) {
        const float ilo = 1.f / ll[mh][0], ihi = 1.f / ll[mh][1];
        const int rlo = m0 + rb + mh * 16 + g;
        const int rhi = rlo + 8;
        __half* clo = g_ctx + ((size_t)(bidx * SEQ + rlo)) * DMODEL + h * HDIM;
        __half* chi = g_ctx + ((size_t)(bidx * SEQ + rhi)) * DMODEL + h * HDIM;
#pragma unroll
        for (int nt = 0; nt < 8; nt++) {
            int c = nt * 8 + 2 * t;
            *(uint32_t*)(clo + c) = cvt2h(o[mh][nt][0] * ilo, o[mh][nt][1] * ilo);
            *(uint32_t*)(chi + c) = cvt2h(o[mh][nt][2] * ihi, o[mh][nt][3] * ihi);
        }
    }
}

// ---------------------------------------------------------------------------
extern "C" void kernel_launch(void* const* d_in, const int* in_sizes, int n_in,
                              void* d_out, int out_size)
{
    const float* x      = (const float*)d_in[0];   // [B,S,D]
    const float* w_qkv  = (const float*)d_in[1];   // [D, 3D]
    const float* b_qkv  = (const float*)d_in[2];   // [3D]
    const float* w_proj = (const float*)d_in[3];   // [D, D]
    const float* b_proj = (const float*)d_in[4];   // [D]
    float* out = (float*)d_out;                    // [B,S,D]

    __half *xh, *wqkvh, *wprojh, *ctxh;
    cudaGetSymbolAddress((void**)&xh, g_x);
    cudaGetSymbolAddress((void**)&wqkvh, g_wqkv);
    cudaGetSymbolAddress((void**)&wprojh, g_wproj);
    cudaGetSymbolAddress((void**)&ctxh, g_ctx);

    cudaFuncSetAttribute(gemm_tc, cudaFuncAttributeMaxDynamicSharedMemorySize, GEMM_SMEM);
    cudaFuncSetAttribute(attn_tc, cudaFuncAttributeMaxDynamicSharedMemorySize, ATT_SMEM);

    // 0) pre-convert inputs to fp16
    to_half_kernel<<<1184, 256>>>((const float4*)x, (uint2*)xh,
                                  MROWS * DMODEL / 4);
    to_half_kernel<<<1184, 256>>>((const float4*)w_qkv, (uint2*)wqkvh,
                                  DMODEL * 3 * DMODEL / 4);
    to_half_kernel<<<1184, 256>>>((const float4*)w_proj, (uint2*)wprojh,
                                  DMODEL * DMODEL / 4);

    // 1) QKV projection -> g_q/g_k/g_v (fp16)
    {
        dim3 grid(3 * DMODEL / 128, MROWS / 128);  // (24, 32)
        gemm_tc<<<grid, 256, GEMM_SMEM>>>(xh, wqkvh, b_qkv, nullptr,
                                          MROWS, 3 * DMODEL, DMODEL, /*mode=*/1);
    }
    // 2) causal attention -> g_ctx (fp16)
    {
        dim3 grid(SEQ / 128, BH);                  // (16, 32)
        attn_tc<<<grid, 128, ATT_SMEM>>>();
    }
    // 3) output projection -> d_out (f32)
    {
        dim3 grid(DMODEL / 128, MROWS / 128);      // (8, 32)
        gemm_tc<<<grid, 256, GEMM_SMEM>>>(ctxh, wprojh, b_proj, out,
                                          MROWS, DMODEL, DMODEL, /*mode=*/0);
    }
    (void)in_sizes; (void)n_in; (void)out_size;
}